// round 17
// baseline (speedup 1.0000x reference)
#include <cuda_runtime.h>
#include <cstdint>

// MeanAggregatorHead: out[b,:] = (1/K) * sum_k tab[idx[b,k],:]
// B=100000, K=32, N=500000, D=128, fp32 table, int32 indices.
//
// FINAL (R16, confirmation run): P=3 kernel-per-pass table chunking.
// - Each pass gathers only rows in one ~85MB table chunk, which stays
//   L2-resident chip-wide for that pass (the kernel boundary is the
//   grid-wide sync that enforces chunk locality).
// - Per-pass: reload raw idx, 3-way ballot bucket-sort (cheap ALU, fully
//   hidden under loads), stage via warp smem, dense 4-wide LDG.128 gather
//   (regs 32, occ ~80%, runs at the ~12.7TB/s path-independent LTS cap).
// - Pass 0 stores the scaled partial; passes 1-2 red.global.add.v4.f32
//   (single writer per element, stream-ordered passes -> deterministic).
// - PDL: trigger after the gather, grid-dependency-sync before touching
//   out. Next pass's prologue overlaps the prior pass's drain tail.
//   Pass 0's sync also orders it after the PREVIOUS graph replay's pass 2.
// Measured: 135.5us vs 174.6us naive single-pass (-22.4%); total L2 bytes
// ~1.83GB with LTS busy end-to-end. Byte floor of the family ~126us is
// unreachable: deleting the partial/idx plumbing requires the smem-
// resident single-kernel design, which ran >=10% below cap in 3 attempts.

constexpr int K       = 32;
constexpr int D       = 128;
constexpr int PASSES  = 3;
constexpr int WPB     = 8;          // warps per block (256 threads)

__device__ __forceinline__ void red_add_f4(float4* p, float4 v) {
    asm volatile("red.global.add.v4.f32 [%0], {%1,%2,%3,%4};"
                 :: "l"(p), "f"(v.x), "f"(v.y), "f"(v.z), "f"(v.w) : "memory");
}

// Dense gather over slots [start, end) of warp-held reordered index v.
// 4-wide batching: 4 independent LDG.128 per iteration, regs stay ~32.
__device__ __forceinline__ float4 dense_gather(
    const float* __restrict__ tab, int v, int lane, int start, int end)
{
    float4 acc = make_float4(0.f, 0.f, 0.f, 0.f);
    int j = start;
    #pragma unroll 1
    for (; j + 4 <= end; j += 4) {
        int r0 = __shfl_sync(0xffffffffu, v, j);
        int r1 = __shfl_sync(0xffffffffu, v, j + 1);
        int r2 = __shfl_sync(0xffffffffu, v, j + 2);
        int r3 = __shfl_sync(0xffffffffu, v, j + 3);
        float4 a0 = __ldg(&reinterpret_cast<const float4*>(tab + (size_t)r0 * D)[lane]);
        float4 a1 = __ldg(&reinterpret_cast<const float4*>(tab + (size_t)r1 * D)[lane]);
        float4 a2 = __ldg(&reinterpret_cast<const float4*>(tab + (size_t)r2 * D)[lane]);
        float4 a3 = __ldg(&reinterpret_cast<const float4*>(tab + (size_t)r3 * D)[lane]);
        acc.x += (a0.x + a1.x) + (a2.x + a3.x);
        acc.y += (a0.y + a1.y) + (a2.y + a3.y);
        acc.z += (a0.z + a1.z) + (a2.z + a3.z);
        acc.w += (a0.w + a1.w) + (a2.w + a3.w);
    }
    #pragma unroll 1
    for (; j < end; ++j) {
        int r = __shfl_sync(0xffffffffu, v, j);
        float4 a = __ldg(&reinterpret_cast<const float4*>(tab + (size_t)r * D)[lane]);
        acc.x += a.x; acc.y += a.y; acc.z += a.z; acc.w += a.w;
    }
    return acc;
}

// One pass: load raw idx, ballot-partition into 3 buckets, gather bucket
// PASS densely. PASS 0 stores the scaled partial; PASS 1-2 red.add theirs.
// Prologue (idx/tab reads only) runs before the grid dependency sync, so
// it may overlap the tail of the previous pass under PDL.
template <int PASS>
__global__ __launch_bounds__(WPB * 32) void agg_pass(
    const float* __restrict__ tab,
    const int*   __restrict__ idx,
    float* __restrict__ out,
    int B, int c1, int c2)
{
    __shared__ int stage[WPB * 32];
    int tid  = threadIdx.x;
    int lane = tid & 31;
    int node = blockIdx.x * WPB + (tid >> 5);

    float4 acc = make_float4(0.f, 0.f, 0.f, 0.f);
    float4* op = nullptr;

    if (node < B) {
        int r = __ldg(&idx[(size_t)node * K + lane]);
        int b = (r >= c1) + (r >= c2);                  // bucket 0..2

        unsigned m0 = __ballot_sync(0xffffffffu, b == 0);
        unsigned m1 = __ballot_sync(0xffffffffu, b == 1);
        unsigned m2 = __ballot_sync(0xffffffffu, b == 2);
        int n0 = __popc(m0), n1 = __popc(m1);

        unsigned lt = (1u << lane) - 1u;
        int slot;
        if      (b == 0) slot = __popc(m0 & lt);
        else if (b == 1) slot = n0 + __popc(m1 & lt);
        else             slot = n0 + n1 + __popc(m2 & lt);

        int* sw = &stage[(tid >> 5) << 5];
        sw[slot] = r;
        __syncwarp();
        int v = sw[lane];                               // reordered index

        int start, end;
        if      (PASS == 0) { start = 0;       end = n0; }
        else if (PASS == 1) { start = n0;      end = n0 + n1; }
        else                { start = n0 + n1; end = K; }

        acc = dense_gather(tab, v, lane, start, end);

        const float s = 1.0f / (float)K;
        acc.x *= s; acc.y *= s; acc.z *= s; acc.w *= s;
        op = &reinterpret_cast<float4*>(out + (size_t)node * D)[lane];
    }

    // Let the next pass launch while this grid drains its epilogue.
    cudaTriggerProgrammaticLaunchCompletion();

    if (op) {
        if (PASS > 0) {
            // out is written by the previous pass: wait for it to complete.
            cudaGridDependencySynchronize();
            red_add_f4(op, acc);       // ordered passes -> deterministic
        } else {
            // Orders this replay's overwrite after the previous graph
            // replay's pass-2 red.add to the same addresses. Load-bearing.
            cudaGridDependencySynchronize();
            *op = acc;                 // overwrite (graph-replay safe)
        }
    }
}

extern "C" void kernel_launch(void* const* d_in, const int* in_sizes, int n_in,
                              void* d_out, int out_size)
{
    // Identify inputs by element count (robust to metadata ordering):
    // embed_table: 64,000,000 ; neigh_idx: 3,200,000 ; num_sample: 1
    long long max_sz = -1, mid_sz = -1;
    int ti = 0, ii = 1;
    for (int i = 0; i < n_in; ++i)
        if (in_sizes[i] > max_sz) { max_sz = in_sizes[i]; ti = i; }
    for (int i = 0; i < n_in; ++i)
        if (i != ti && in_sizes[i] > mid_sz) { mid_sz = in_sizes[i]; ii = i; }

    const float* tab = (const float*)d_in[ti];
    const int*   idx = (const int*)d_in[ii];
    float*       out = (float*)d_out;

    int B = out_size / D;                    // 100000
    int N = (int)(max_sz / D);               // 500000 table rows
    int chunk = (N + PASSES - 1) / PASSES;   // 166667 rows ~ 85MB

    int blocks = (B + WPB - 1) / WPB;        // 12500

    cudaLaunchAttribute attrs[1];
    attrs[0].id = cudaLaunchAttributeProgrammaticStreamSerialization;
    attrs[0].val.programmaticStreamSerializationAllowed = 1;

    cudaLaunchConfig_t cfg = {};
    cfg.gridDim  = dim3((unsigned)blocks, 1, 1);
    cfg.blockDim = dim3(WPB * 32, 1, 1);
    cfg.dynamicSmemBytes = 0;
    cfg.stream = 0;
    cfg.attrs = attrs;
    cfg.numAttrs = 1;

    cudaLaunchKernelEx(&cfg, agg_pass<0>, tab, idx, out, B, chunk, 2 * chunk);
    cudaLaunchKernelEx(&cfg, agg_pass<1>, tab, idx, out, B, chunk, 2 * chunk);
    cudaLaunchKernelEx(&cfg, agg_pass<2>, tab, idx, out, B, chunk, 2 * chunk);
}